// round 10
// baseline (speedup 1.0000x reference)
#include <cuda_runtime.h>
#include <cuda_fp16.h>
#include <math.h>

// ---------------------------------------------------------------------------
// CrossCBR propagation — unified-CSR, fp16 data / fp32 accumulate.
// R10: warp-per-row gather with 4 edges in flight (lane-group rotation),
// eliminating cross-row dmax predication waste. fp32 accumulation (R9's
// HADD2 register blowup reverted).
// ---------------------------------------------------------------------------
#define NU 100000
#define NI 200000
#define NB 50000
#define FD 64
#define E_UI 1000000
#define E_UB 500000
#define E_BI 1000000

#define B0 0
#define B1 NU                    // 100000
#define B2 (NU + NI)             // 300000
#define B3 (NU + NI + NU)        // 400000
#define B4 (NU + NI + NU + NB)   // 450000
#define NTOT (B4 + NB)           // 500000
#define NPROP B4
#define E_TOT (2 * E_UI + 2 * E_UB + E_BI)   // 4,000,000

#define SCAN_T 1024
#define SCAN_NB ((NTOT + SCAN_T - 1) / SCAN_T)   // 489

// ---------------------------------------------------------------------------
// Static device scratch (BSS zero on load; cnt/tstat re-zeroed each call).
// ---------------------------------------------------------------------------
__device__ int    g_cnt[NTOT];
__device__ int    g_cur[NTOT];
__device__ int    g_ptr[NTOT + 1];
__device__ int    g_col[E_TOT];
__device__ unsigned long long g_tstat[512];
__device__ float  g_inv1[NPROP];
__device__ uint4  g_hu[NU * 8];           // users   fp16
__device__ uint4  g_hi[NI * 8];           // items   fp16
__device__ uint4  g_hb[NB * 8];           // bundles fp16
__device__ uint4  g_f1h[NPROP * 8];       // layer-1 outputs fp16
__device__ uint4  g_aIh[NI * 8];          // item-level item acc fp16

// ---------------------------------------------------------------------------
// fp16 helpers
// ---------------------------------------------------------------------------
__device__ __forceinline__ unsigned f2h(float x, float y) {
    __half2 h = __floats2half2_rn(x, y);
    return *reinterpret_cast<unsigned*>(&h);
}
__device__ __forceinline__ float2 h2f(unsigned u) {
    __half2 h = *reinterpret_cast<__half2*>(&u);
    return __half22float2(h);
}
__device__ __forceinline__ uint4 pack8(const float4* __restrict__ s, int i) {
    float4 a = __ldcs(&s[2 * i]), b = __ldcs(&s[2 * i + 1]);
    uint4 u;
    u.x = f2h(a.x, a.y); u.y = f2h(a.z, a.w);
    u.z = f2h(b.x, b.y); u.w = f2h(b.z, b.w);
    return u;
}

// ---------------------------------------------------------------------------
// Fused count + fp16 conversion
// ---------------------------------------------------------------------------
#define Q_UI (E_UI / 4)
#define Q_UB (E_UB / 4)
#define Q_BI (E_BI / 4)
#define Q_TOT (Q_UI + Q_UB + Q_BI)
#define CVT_U (NU * 8)
#define CVT_I (NI * 8)
#define CVT_B (NB * 8)
#define WORK_TOT (Q_TOT + CVT_U + CVT_I + CVT_B)

__global__ void k_count_cvt(const int4* __restrict__ ui_row, const int4* __restrict__ ui_col,
                            const int4* __restrict__ ub_row, const int4* __restrict__ ub_col,
                            const int4* __restrict__ bi_row,
                            const float4* __restrict__ users, const float4* __restrict__ items,
                            const float4* __restrict__ bundles) {
    int i = blockIdx.x * blockDim.x + threadIdx.x;
    int stride = gridDim.x * blockDim.x;
    for (; i < WORK_TOT; i += stride) {
        if (i < Q_UI) {
            int4 r = __ldcs(&ui_row[i]), c = __ldcs(&ui_col[i]);
            atomicAdd(&g_cnt[r.x], 1); atomicAdd(&g_cnt[r.y], 1);
            atomicAdd(&g_cnt[r.z], 1); atomicAdd(&g_cnt[r.w], 1);
            atomicAdd(&g_cnt[B1 + c.x], 1); atomicAdd(&g_cnt[B1 + c.y], 1);
            atomicAdd(&g_cnt[B1 + c.z], 1); atomicAdd(&g_cnt[B1 + c.w], 1);
        } else if (i < Q_UI + Q_UB) {
            int e = i - Q_UI;
            int4 r = __ldcs(&ub_row[e]), c = __ldcs(&ub_col[e]);
            atomicAdd(&g_cnt[B2 + r.x], 1); atomicAdd(&g_cnt[B2 + r.y], 1);
            atomicAdd(&g_cnt[B2 + r.z], 1); atomicAdd(&g_cnt[B2 + r.w], 1);
            atomicAdd(&g_cnt[B3 + c.x], 1); atomicAdd(&g_cnt[B3 + c.y], 1);
            atomicAdd(&g_cnt[B3 + c.z], 1); atomicAdd(&g_cnt[B3 + c.w], 1);
        } else if (i < Q_TOT) {
            int e = i - Q_UI - Q_UB;
            int4 r = __ldcs(&bi_row[e]);
            atomicAdd(&g_cnt[B4 + r.x], 1); atomicAdd(&g_cnt[B4 + r.y], 1);
            atomicAdd(&g_cnt[B4 + r.z], 1); atomicAdd(&g_cnt[B4 + r.w], 1);
        } else {
            int j = i - Q_TOT;
            if (j < CVT_U)               g_hu[j] = pack8(users, j);
            else if (j < CVT_U + CVT_I)  g_hi[j - CVT_U] = pack8(items, j - CVT_U);
            else                         g_hb[j - CVT_U - CVT_I] = pack8(bundles, j - CVT_U - CVT_I);
        }
    }
}

// ---------------------------------------------------------------------------
// Single-pass decoupled-lookback scan: cnt -> ptr (exclusive) + cur.
// ---------------------------------------------------------------------------
__global__ void __launch_bounds__(SCAN_T)
k_scan_lb() {
    __shared__ int wscan[32];
    __shared__ unsigned s_base;
    int tid = threadIdx.x, lane = tid & 31, wid = tid >> 5;
    int bid = blockIdx.x;
    int i = bid * SCAN_T + tid;
    int v = (i < NTOT) ? g_cnt[i] : 0;

    int x = v;
    #pragma unroll
    for (int o = 1; o < 32; o <<= 1) {
        int t = __shfl_up_sync(0xffffffffu, x, o);
        if (lane >= o) x += t;
    }
    if (lane == 31) wscan[wid] = x;
    __syncthreads();
    if (wid == 0) {
        int y = wscan[lane];
        #pragma unroll
        for (int o = 1; o < 32; o <<= 1) {
            int t = __shfl_up_sync(0xffffffffu, y, o);
            if (lane >= o) y += t;
        }
        wscan[lane] = y;
    }
    __syncthreads();
    int warpbase = (wid > 0) ? wscan[wid - 1] : 0;
    int incl = warpbase + x;
    unsigned agg = (unsigned)wscan[31];

    if (tid == 0 && bid > 0)
        atomicExch(&g_tstat[bid], (1ULL << 32) | (unsigned long long)agg);

    if (wid == 0) {
        unsigned run = 0;
        if (bid > 0) {
            int j = bid - 1;
            while (j >= 0) {
                int idx = j - lane;
                bool active = idx >= 0;
                unsigned long long s = 0;
                while (true) {
                    if (active) s = atomicAdd(&g_tstat[idx], 0ULL);
                    unsigned zm = __ballot_sync(0xffffffffu, active && (unsigned)(s >> 32) == 0u);
                    if (zm == 0) break;
                }
                unsigned pm = __ballot_sync(0xffffffffu, active && (unsigned)(s >> 32) == 2u);
                unsigned contrib;
                if (pm) {
                    int L = __ffs(pm) - 1;
                    contrib = (lane <= L) ? (unsigned)s : 0u;
                } else {
                    contrib = active ? (unsigned)s : 0u;
                }
                #pragma unroll
                for (int o = 16; o >= 1; o >>= 1)
                    contrib += __shfl_xor_sync(0xffffffffu, contrib, o);
                run += contrib;
                if (pm) break;
                j -= 32;
            }
        }
        if (lane == 0) {
            s_base = run;
            atomicExch(&g_tstat[bid], (2ULL << 32) | (unsigned long long)(run + agg));
        }
    }
    __syncthreads();

    int excl = (int)s_base + incl - v;
    if (i < NTOT) { g_ptr[i] = excl; g_cur[i] = excl; }
    if (i == NTOT - 1) g_ptr[NTOT] = E_TOT;
}

// ---------------------------------------------------------------------------
// Scatter; tail re-zeroes cnt/tstat for the next call.
// ---------------------------------------------------------------------------
__global__ void k_scatter(const int4* __restrict__ ui_row, const int4* __restrict__ ui_col,
                          const int4* __restrict__ ub_row, const int4* __restrict__ ub_col,
                          const int4* __restrict__ bi_row, const int4* __restrict__ bi_col) {
    int i = blockIdx.x * blockDim.x + threadIdx.x;
    int stride = gridDim.x * blockDim.x;
    for (int w = i; w < Q_TOT; w += stride) {
        if (w < Q_UI) {
            int4 r = __ldcs(&ui_row[w]), c = __ldcs(&ui_col[w]);
            g_col[atomicAdd(&g_cur[r.x], 1)] = c.x;
            g_col[atomicAdd(&g_cur[r.y], 1)] = c.y;
            g_col[atomicAdd(&g_cur[r.z], 1)] = c.z;
            g_col[atomicAdd(&g_cur[r.w], 1)] = c.w;
            g_col[atomicAdd(&g_cur[B1 + c.x], 1)] = r.x;
            g_col[atomicAdd(&g_cur[B1 + c.y], 1)] = r.y;
            g_col[atomicAdd(&g_cur[B1 + c.z], 1)] = r.z;
            g_col[atomicAdd(&g_cur[B1 + c.w], 1)] = r.w;
        } else if (w < Q_UI + Q_UB) {
            int e = w - Q_UI;
            int4 r = __ldcs(&ub_row[e]), c = __ldcs(&ub_col[e]);
            g_col[atomicAdd(&g_cur[B2 + r.x], 1)] = c.x;
            g_col[atomicAdd(&g_cur[B2 + r.y], 1)] = c.y;
            g_col[atomicAdd(&g_cur[B2 + r.z], 1)] = c.z;
            g_col[atomicAdd(&g_cur[B2 + r.w], 1)] = c.w;
            g_col[atomicAdd(&g_cur[B3 + c.x], 1)] = r.x;
            g_col[atomicAdd(&g_cur[B3 + c.y], 1)] = r.y;
            g_col[atomicAdd(&g_cur[B3 + c.z], 1)] = r.z;
            g_col[atomicAdd(&g_cur[B3 + c.w], 1)] = r.w;
        } else {
            int e = w - Q_UI - Q_UB;
            int4 r = __ldcs(&bi_row[e]), c = __ldcs(&bi_col[e]);
            g_col[atomicAdd(&g_cur[B4 + r.x], 1)] = c.x;
            g_col[atomicAdd(&g_cur[B4 + r.y], 1)] = c.y;
            g_col[atomicAdd(&g_cur[B4 + r.z], 1)] = c.z;
            g_col[atomicAdd(&g_cur[B4 + r.w], 1)] = c.w;
        }
    }
    for (int w = i; w < NTOT; w += stride) g_cnt[w] = 0;
    for (int w = i; w < 512; w += stride) g_tstat[w] = 0ULL;
}

// ---------------------------------------------------------------------------
// Warp-per-row gather, 4 edges in flight.
// Lane group g = lane>>3 handles edges g, g+4, g+8, ...; each group holds a
// full row replica (8 lanes x uint4 slice hl = lane&7). Cross-group combine
// via shfl_xor(8,16) at the end. fp32 accumulation.
// ---------------------------------------------------------------------------
__device__ __forceinline__ void gather_warp_row(const uint4* __restrict__ src,
                                                int beg, int deg, int grp, int hl,
                                                float2 acc[4]) {
    const int* __restrict__ cols = g_col;
    acc[0] = acc[1] = acc[2] = acc[3] = make_float2(0.f, 0.f);
    int nIt = (deg + 3) >> 2;          // warp-uniform trip count
    for (int it = 0; it < nIt; it += 2) {
        int i0 = (it << 2) + grp;
        int i1 = i0 + 4;
        bool p0 = i0 < deg, p1 = (it + 1 < nIt) && (i1 < deg);
        uint4 v0 = make_uint4(0u,0u,0u,0u), v1 = make_uint4(0u,0u,0u,0u);
        if (p0) v0 = src[cols[beg + i0] * 8 + hl];
        if (p1) v1 = src[cols[beg + i1] * 8 + hl];
        if (p0) {
            float2 f0 = h2f(v0.x), f1 = h2f(v0.y), f2 = h2f(v0.z), f3 = h2f(v0.w);
            acc[0].x += f0.x; acc[0].y += f0.y;
            acc[1].x += f1.x; acc[1].y += f1.y;
            acc[2].x += f2.x; acc[2].y += f2.y;
            acc[3].x += f3.x; acc[3].y += f3.y;
        }
        if (p1) {
            float2 f0 = h2f(v1.x), f1 = h2f(v1.y), f2 = h2f(v1.z), f3 = h2f(v1.w);
            acc[0].x += f0.x; acc[0].y += f0.y;
            acc[1].x += f1.x; acc[1].y += f1.y;
            acc[2].x += f2.x; acc[2].y += f2.y;
            acc[3].x += f3.x; acc[3].y += f3.y;
        }
    }
    // combine the 4 group replicas (all lanes end with the full row slice)
    #pragma unroll
    for (int o = 8; o <= 16; o <<= 1) {
        #pragma unroll
        for (int j = 0; j < 4; j++) {
            acc[j].x += __shfl_xor_sync(0xffffffffu, acc[j].x, o);
            acc[j].y += __shfl_xor_sync(0xffffffffu, acc[j].y, o);
        }
    }
}

// norm over the 8-lane slice group (after combine all groups identical)
__device__ __forceinline__ float row_inv_norm(const float2 a[4]) {
    float sq = a[0].x * a[0].x + a[0].y * a[0].y + a[1].x * a[1].x + a[1].y * a[1].y
             + a[2].x * a[2].x + a[2].y * a[2].y + a[3].x * a[3].x + a[3].y * a[3].y;
    #pragma unroll
    for (int o = 4; o >= 1; o >>= 1) sq += __shfl_xor_sync(0xffffffffu, sq, o);
    return 1.0f / fmaxf(sqrtf(sq), 1e-12f);
}

// layer1: feat1[r] = gather(src_seg) -> fp16; inv1[r] = 1/max(||feat1[r]||,eps)
__global__ void __launch_bounds__(256)
k_layer1() {
    int r = (blockIdx.x * blockDim.x + threadIdx.x) >> 5;
    if (r >= NPROP) return;
    int lane = threadIdx.x & 31;
    int hl = lane & 7, grp = lane >> 3;

    int beg = g_ptr[r], deg = g_ptr[r + 1] - beg;

    const uint4* src;
    if (r < B1)      src = g_hi;
    else if (r < B2) src = g_hu;
    else if (r < B3) src = g_hb;
    else             src = g_hu;

    float2 acc[4];
    gather_warp_row(src, beg, deg, grp, hl, acc);

    if (grp == 0) {
        uint4 p;
        p.x = f2h(acc[0].x, acc[0].y); p.y = f2h(acc[1].x, acc[1].y);
        p.z = f2h(acc[2].x, acc[2].y); p.w = f2h(acc[3].x, acc[3].y);
        g_f1h[r * 8 + hl] = p;
    }
    float inv = row_inv_norm(acc);
    if (lane == 0) g_inv1[r] = inv;
}

// layer2: final = (base + feat1*inv1) + norm(gather(feat1_other_seg))
__global__ void __launch_bounds__(256)
k_layer2(float* __restrict__ out) {
    int r = (blockIdx.x * blockDim.x + threadIdx.x) >> 5;
    if (r >= NPROP) return;
    int lane = threadIdx.x & 31;
    int hl = lane & 7, grp = lane >> 3;

    int beg = g_ptr[r], deg = g_ptr[r + 1] - beg;

    const uint4* src;
    const uint4* base;
    if (r < B1)      { src = g_f1h + B1 * 8; base = g_hu + r * 8; }
    else if (r < B2) { src = g_f1h;          base = g_hi + (r - B1) * 8; }
    else if (r < B3) { src = g_f1h + B3 * 8; base = g_hu + (r - B2) * 8; }
    else             { src = g_f1h + B2 * 8; base = g_hb + (r - B3) * 8; }

    float2 acc[4];
    gather_warp_row(src, beg, deg, grp, hl, acc);
    float inv = row_inv_norm(acc);

    // a0 = base + feat1 * inv1 ; v = a0 + acc*inv  (only group 0 writes)
    uint4 bh = base[hl];
    uint4 fh = g_f1h[r * 8 + hl];
    float inv1 = g_inv1[r];
    float2 v[4];
    {
        float2 b0 = h2f(bh.x), b1 = h2f(bh.y), b2 = h2f(bh.z), b3 = h2f(bh.w);
        float2 f0 = h2f(fh.x), f1 = h2f(fh.y), f2 = h2f(fh.z), f3 = h2f(fh.w);
        v[0] = make_float2(b0.x + f0.x * inv1 + acc[0].x * inv, b0.y + f0.y * inv1 + acc[0].y * inv);
        v[1] = make_float2(b1.x + f1.x * inv1 + acc[1].x * inv, b1.y + f1.y * inv1 + acc[1].y * inv);
        v[2] = make_float2(b2.x + f2.x * inv1 + acc[2].x * inv, b2.y + f2.y * inv1 + acc[2].y * inv);
        v[3] = make_float2(b3.x + f3.x * inv1 + acc[3].x * inv, b3.y + f3.y * inv1 + acc[3].y * inv);
    }

    if (grp == 0) {
        if (r >= B1 && r < B2) {
            uint4 p;
            p.x = f2h(v[0].x, v[0].y); p.y = f2h(v[1].x, v[1].y);
            p.z = f2h(v[2].x, v[2].y); p.w = f2h(v[3].x, v[3].y);
            g_aIh[(r - B1) * 8 + hl] = p;
        } else {
            float4 o0 = make_float4(v[0].x, v[0].y, v[1].x, v[1].y);
            float4 o1 = make_float4(v[2].x, v[2].y, v[3].x, v[3].y);
            float4* out4 = (float4*)out;
            int slot;
            if (r < B1)      slot = r * 32 + hl * 2;
            else if (r < B3) slot = (r - B2) * 32 + 16 + hl * 2;
            else             slot = (NU + r - B3) * 32 + 16 + hl * 2;
            __stcs(&out4[slot], o0);
            __stcs(&out4[slot + 1], o1);
        }
    }
}

// rowmean: out[bundle, 0:64) = (1/(deg+1e-8)) * sum accI[i]
__global__ void __launch_bounds__(256)
k_rowmean(float* __restrict__ out) {
    int b = (blockIdx.x * blockDim.x + threadIdx.x) >> 5;
    if (b >= NB) return;
    int lane = threadIdx.x & 31;
    int hl = lane & 7, grp = lane >> 3;
    int r = B4 + b;

    int beg = g_ptr[r], deg = g_ptr[r + 1] - beg;

    float2 acc[4];
    gather_warp_row(g_aIh, beg, deg, grp, hl, acc);

    if (grp == 0) {
        float inv = 1.0f / ((float)deg + 1e-8f);
        float4 o0 = make_float4(acc[0].x * inv, acc[0].y * inv, acc[1].x * inv, acc[1].y * inv);
        float4 o1 = make_float4(acc[2].x * inv, acc[2].y * inv, acc[3].x * inv, acc[3].y * inv);
        float4* out4 = (float4*)out;
        int slot = (NU + b) * 32 + hl * 2;
        __stcs(&out4[slot], o0);
        __stcs(&out4[slot + 1], o1);
    }
}

// ---------------------------------------------------------------------------
// Host launch sequence (graph-capturable, 6 launches)
// ---------------------------------------------------------------------------
extern "C" void kernel_launch(void* const* d_in, const int* in_sizes, int n_in,
                              void* d_out, int out_size) {
    const float4* users   = (const float4*)d_in[0];
    const float4* items   = (const float4*)d_in[1];
    const float4* bundles = (const float4*)d_in[2];
    const int4* ui_row = (const int4*)d_in[3];
    const int4* ui_col = (const int4*)d_in[4];
    const int4* ub_row = (const int4*)d_in[5];
    const int4* ub_col = (const int4*)d_in[6];
    const int4* bi_row = (const int4*)d_in[7];
    const int4* bi_col = (const int4*)d_in[8];
    float* out = (float*)d_out;

    const int T = 256;

    k_count_cvt<<<2048, T>>>(ui_row, ui_col, ub_row, ub_col, bi_row,
                             users, items, bundles);
    k_scan_lb<<<SCAN_NB, SCAN_T>>>();
    k_scatter<<<1024, T>>>(ui_row, ui_col, ub_row, ub_col, bi_row, bi_col);

    // warp per row: 8 rows per 256-thread block
    k_layer1<<<(NPROP + 7) / 8, T>>>();
    k_layer2<<<(NPROP + 7) / 8, T>>>(out);
    k_rowmean<<<(NB + 7) / 8, T>>>(out);
}

// round 11
// speedup vs baseline: 1.7441x; 1.7441x over previous
#include <cuda_runtime.h>
#include <cuda_fp16.h>
#include <math.h>

// ---------------------------------------------------------------------------
// CrossCBR propagation — unified-CSR, fp16 data.
// R11 = R8 structure (4 rows/warp, 8-lane groups, dmax predication)
//       + 2-way-split HADD2 accumulation (8 acc regs, fp32 combine per row).
// ---------------------------------------------------------------------------
#define NU 100000
#define NI 200000
#define NB 50000
#define FD 64
#define E_UI 1000000
#define E_UB 500000
#define E_BI 1000000

#define B0 0
#define B1 NU                    // 100000
#define B2 (NU + NI)             // 300000
#define B3 (NU + NI + NU)        // 400000
#define B4 (NU + NI + NU + NB)   // 450000
#define NTOT (B4 + NB)           // 500000
#define NPROP B4
#define E_TOT (2 * E_UI + 2 * E_UB + E_BI)   // 4,000,000

#define SCAN_T 1024
#define SCAN_NB ((NTOT + SCAN_T - 1) / SCAN_T)   // 489

// ---------------------------------------------------------------------------
// Static device scratch (BSS zero on load; cnt/tstat re-zeroed each call).
// ---------------------------------------------------------------------------
__device__ int    g_cnt[NTOT];
__device__ int    g_cur[NTOT];
__device__ int    g_ptr[NTOT + 1];
__device__ int    g_col[E_TOT];
__device__ unsigned long long g_tstat[512];
__device__ float  g_inv1[NPROP];
__device__ uint4  g_hu[NU * 8];           // users   fp16
__device__ uint4  g_hi[NI * 8];           // items   fp16
__device__ uint4  g_hb[NB * 8];           // bundles fp16
__device__ uint4  g_f1h[NPROP * 8];       // layer-1 outputs fp16
__device__ uint4  g_aIh[NI * 8];          // item-level item acc fp16

// ---------------------------------------------------------------------------
// fp16 helpers
// ---------------------------------------------------------------------------
__device__ __forceinline__ unsigned f2h(float x, float y) {
    __half2 h = __floats2half2_rn(x, y);
    return *reinterpret_cast<unsigned*>(&h);
}
__device__ __forceinline__ float2 h2f(unsigned u) {
    __half2 h = *reinterpret_cast<__half2*>(&u);
    return __half22float2(h);
}
__device__ __forceinline__ unsigned hadd2u(unsigned a, unsigned b) {
    __half2 r = __hadd2(*reinterpret_cast<__half2*>(&a), *reinterpret_cast<__half2*>(&b));
    return *reinterpret_cast<unsigned*>(&r);
}
__device__ __forceinline__ uint4 pack8(const float4* __restrict__ s, int i) {
    float4 a = __ldcs(&s[2 * i]), b = __ldcs(&s[2 * i + 1]);
    uint4 u;
    u.x = f2h(a.x, a.y); u.y = f2h(a.z, a.w);
    u.z = f2h(b.x, b.y); u.w = f2h(b.z, b.w);
    return u;
}

// ---------------------------------------------------------------------------
// Fused count + fp16 conversion
// ---------------------------------------------------------------------------
#define Q_UI (E_UI / 4)
#define Q_UB (E_UB / 4)
#define Q_BI (E_BI / 4)
#define Q_TOT (Q_UI + Q_UB + Q_BI)
#define CVT_U (NU * 8)
#define CVT_I (NI * 8)
#define CVT_B (NB * 8)
#define WORK_TOT (Q_TOT + CVT_U + CVT_I + CVT_B)

__global__ void k_count_cvt(const int4* __restrict__ ui_row, const int4* __restrict__ ui_col,
                            const int4* __restrict__ ub_row, const int4* __restrict__ ub_col,
                            const int4* __restrict__ bi_row,
                            const float4* __restrict__ users, const float4* __restrict__ items,
                            const float4* __restrict__ bundles) {
    int i = blockIdx.x * blockDim.x + threadIdx.x;
    int stride = gridDim.x * blockDim.x;
    for (; i < WORK_TOT; i += stride) {
        if (i < Q_UI) {
            int4 r = __ldcs(&ui_row[i]), c = __ldcs(&ui_col[i]);
            atomicAdd(&g_cnt[r.x], 1); atomicAdd(&g_cnt[r.y], 1);
            atomicAdd(&g_cnt[r.z], 1); atomicAdd(&g_cnt[r.w], 1);
            atomicAdd(&g_cnt[B1 + c.x], 1); atomicAdd(&g_cnt[B1 + c.y], 1);
            atomicAdd(&g_cnt[B1 + c.z], 1); atomicAdd(&g_cnt[B1 + c.w], 1);
        } else if (i < Q_UI + Q_UB) {
            int e = i - Q_UI;
            int4 r = __ldcs(&ub_row[e]), c = __ldcs(&ub_col[e]);
            atomicAdd(&g_cnt[B2 + r.x], 1); atomicAdd(&g_cnt[B2 + r.y], 1);
            atomicAdd(&g_cnt[B2 + r.z], 1); atomicAdd(&g_cnt[B2 + r.w], 1);
            atomicAdd(&g_cnt[B3 + c.x], 1); atomicAdd(&g_cnt[B3 + c.y], 1);
            atomicAdd(&g_cnt[B3 + c.z], 1); atomicAdd(&g_cnt[B3 + c.w], 1);
        } else if (i < Q_TOT) {
            int e = i - Q_UI - Q_UB;
            int4 r = __ldcs(&bi_row[e]);
            atomicAdd(&g_cnt[B4 + r.x], 1); atomicAdd(&g_cnt[B4 + r.y], 1);
            atomicAdd(&g_cnt[B4 + r.z], 1); atomicAdd(&g_cnt[B4 + r.w], 1);
        } else {
            int j = i - Q_TOT;
            if (j < CVT_U)               g_hu[j] = pack8(users, j);
            else if (j < CVT_U + CVT_I)  g_hi[j - CVT_U] = pack8(items, j - CVT_U);
            else                         g_hb[j - CVT_U - CVT_I] = pack8(bundles, j - CVT_U - CVT_I);
        }
    }
}

// ---------------------------------------------------------------------------
// Single-pass decoupled-lookback scan: cnt -> ptr (exclusive) + cur.
// ---------------------------------------------------------------------------
__global__ void __launch_bounds__(SCAN_T)
k_scan_lb() {
    __shared__ int wscan[32];
    __shared__ unsigned s_base;
    int tid = threadIdx.x, lane = tid & 31, wid = tid >> 5;
    int bid = blockIdx.x;
    int i = bid * SCAN_T + tid;
    int v = (i < NTOT) ? g_cnt[i] : 0;

    int x = v;
    #pragma unroll
    for (int o = 1; o < 32; o <<= 1) {
        int t = __shfl_up_sync(0xffffffffu, x, o);
        if (lane >= o) x += t;
    }
    if (lane == 31) wscan[wid] = x;
    __syncthreads();
    if (wid == 0) {
        int y = wscan[lane];
        #pragma unroll
        for (int o = 1; o < 32; o <<= 1) {
            int t = __shfl_up_sync(0xffffffffu, y, o);
            if (lane >= o) y += t;
        }
        wscan[lane] = y;
    }
    __syncthreads();
    int warpbase = (wid > 0) ? wscan[wid - 1] : 0;
    int incl = warpbase + x;
    unsigned agg = (unsigned)wscan[31];

    if (tid == 0 && bid > 0)
        atomicExch(&g_tstat[bid], (1ULL << 32) | (unsigned long long)agg);

    if (wid == 0) {
        unsigned run = 0;
        if (bid > 0) {
            int j = bid - 1;
            while (j >= 0) {
                int idx = j - lane;
                bool active = idx >= 0;
                unsigned long long s = 0;
                while (true) {
                    if (active) s = atomicAdd(&g_tstat[idx], 0ULL);
                    unsigned zm = __ballot_sync(0xffffffffu, active && (unsigned)(s >> 32) == 0u);
                    if (zm == 0) break;
                }
                unsigned pm = __ballot_sync(0xffffffffu, active && (unsigned)(s >> 32) == 2u);
                unsigned contrib;
                if (pm) {
                    int L = __ffs(pm) - 1;
                    contrib = (lane <= L) ? (unsigned)s : 0u;
                } else {
                    contrib = active ? (unsigned)s : 0u;
                }
                #pragma unroll
                for (int o = 16; o >= 1; o >>= 1)
                    contrib += __shfl_xor_sync(0xffffffffu, contrib, o);
                run += contrib;
                if (pm) break;
                j -= 32;
            }
        }
        if (lane == 0) {
            s_base = run;
            atomicExch(&g_tstat[bid], (2ULL << 32) | (unsigned long long)(run + agg));
        }
    }
    __syncthreads();

    int excl = (int)s_base + incl - v;
    if (i < NTOT) { g_ptr[i] = excl; g_cur[i] = excl; }
    if (i == NTOT - 1) g_ptr[NTOT] = E_TOT;
}

// ---------------------------------------------------------------------------
// Scatter; tail re-zeroes cnt/tstat for the next call.
// ---------------------------------------------------------------------------
__global__ void k_scatter(const int4* __restrict__ ui_row, const int4* __restrict__ ui_col,
                          const int4* __restrict__ ub_row, const int4* __restrict__ ub_col,
                          const int4* __restrict__ bi_row, const int4* __restrict__ bi_col) {
    int i = blockIdx.x * blockDim.x + threadIdx.x;
    int stride = gridDim.x * blockDim.x;
    for (int w = i; w < Q_TOT; w += stride) {
        if (w < Q_UI) {
            int4 r = __ldcs(&ui_row[w]), c = __ldcs(&ui_col[w]);
            g_col[atomicAdd(&g_cur[r.x], 1)] = c.x;
            g_col[atomicAdd(&g_cur[r.y], 1)] = c.y;
            g_col[atomicAdd(&g_cur[r.z], 1)] = c.z;
            g_col[atomicAdd(&g_cur[r.w], 1)] = c.w;
            g_col[atomicAdd(&g_cur[B1 + c.x], 1)] = r.x;
            g_col[atomicAdd(&g_cur[B1 + c.y], 1)] = r.y;
            g_col[atomicAdd(&g_cur[B1 + c.z], 1)] = r.z;
            g_col[atomicAdd(&g_cur[B1 + c.w], 1)] = r.w;
        } else if (w < Q_UI + Q_UB) {
            int e = w - Q_UI;
            int4 r = __ldcs(&ub_row[e]), c = __ldcs(&ub_col[e]);
            g_col[atomicAdd(&g_cur[B2 + r.x], 1)] = c.x;
            g_col[atomicAdd(&g_cur[B2 + r.y], 1)] = c.y;
            g_col[atomicAdd(&g_cur[B2 + r.z], 1)] = c.z;
            g_col[atomicAdd(&g_cur[B2 + r.w], 1)] = c.w;
            g_col[atomicAdd(&g_cur[B3 + c.x], 1)] = r.x;
            g_col[atomicAdd(&g_cur[B3 + c.y], 1)] = r.y;
            g_col[atomicAdd(&g_cur[B3 + c.z], 1)] = r.z;
            g_col[atomicAdd(&g_cur[B3 + c.w], 1)] = r.w;
        } else {
            int e = w - Q_UI - Q_UB;
            int4 r = __ldcs(&bi_row[e]), c = __ldcs(&bi_col[e]);
            g_col[atomicAdd(&g_cur[B4 + r.x], 1)] = c.x;
            g_col[atomicAdd(&g_cur[B4 + r.y], 1)] = c.y;
            g_col[atomicAdd(&g_cur[B4 + r.z], 1)] = c.z;
            g_col[atomicAdd(&g_cur[B4 + r.w], 1)] = c.w;
        }
    }
    for (int w = i; w < NTOT; w += stride) g_cnt[w] = 0;
    for (int w = i; w < 512; w += stride) g_tstat[w] = 0ULL;
}

// ---------------------------------------------------------------------------
// Gathers: warp handles rows (4w..4w+3); 8-lane group per row; lane holds a
// uint4 (8 halves, 16B) slice of the 128B row. dmax = pairwise max degree.
// ---------------------------------------------------------------------------
__device__ __forceinline__ int row_dmax(int deg) {
    int d = max(deg, __shfl_xor_sync(0xffffffffu, deg, 8));
    return max(d, __shfl_xor_sync(0xffffffffu, d, 16));
}

// 2-way-split HADD2 accumulation: edges alternate between sets a0/a1
// (8 unsigned regs total); fp32 combine at row end. Skipped edges add nothing.
__device__ __forceinline__ void gather_row_hh2(const uint4* __restrict__ src,
                                               int beg, int deg, int dmax, int hl,
                                               float2 facc[4]) {
    const int* __restrict__ cols = g_col;
    unsigned a0[4] = {0u,0u,0u,0u};
    unsigned a1[4] = {0u,0u,0u,0u};
    for (int jj = 0; jj < dmax; jj += 4) {
        #pragma unroll
        for (int k = 0; k < 4; k++) {
            if (jj + k < deg) {
                int c = cols[beg + jj + k];
                uint4 v = src[c * 8 + hl];
                if (k & 1) {
                    a1[0] = hadd2u(a1[0], v.x); a1[1] = hadd2u(a1[1], v.y);
                    a1[2] = hadd2u(a1[2], v.z); a1[3] = hadd2u(a1[3], v.w);
                } else {
                    a0[0] = hadd2u(a0[0], v.x); a0[1] = hadd2u(a0[1], v.y);
                    a0[2] = hadd2u(a0[2], v.z); a0[3] = hadd2u(a0[3], v.w);
                }
            }
        }
    }
    #pragma unroll
    for (int j = 0; j < 4; j++) {
        float2 p = h2f(a0[j]), q = h2f(a1[j]);
        facc[j] = make_float2(p.x + q.x, p.y + q.y);
    }
}

// fp32 accumulation gather (rowmean — largest magnitudes)
__device__ __forceinline__ void gather_row_h(const uint4* __restrict__ src,
                                             int beg, int deg, int dmax, int hl,
                                             float2 acc[4]) {
    const int* __restrict__ cols = g_col;
    for (int jj = 0; jj < dmax; jj += 8) {
        #pragma unroll
        for (int k = 0; k < 8; k++) {
            if (jj + k < deg) {
                int c = cols[beg + jj + k];
                uint4 v = src[c * 8 + hl];
                float2 f0 = h2f(v.x), f1 = h2f(v.y), f2 = h2f(v.z), f3 = h2f(v.w);
                acc[0].x += f0.x; acc[0].y += f0.y;
                acc[1].x += f1.x; acc[1].y += f1.y;
                acc[2].x += f2.x; acc[2].y += f2.y;
                acc[3].x += f3.x; acc[3].y += f3.y;
            }
        }
    }
}

__device__ __forceinline__ float row_inv_norm(const float2 a[4]) {
    float sq = a[0].x * a[0].x + a[0].y * a[0].y + a[1].x * a[1].x + a[1].y * a[1].y
             + a[2].x * a[2].x + a[2].y * a[2].y + a[3].x * a[3].x + a[3].y * a[3].y;
    #pragma unroll
    for (int o = 4; o >= 1; o >>= 1) sq += __shfl_xor_sync(0xffffffffu, sq, o);
    return 1.0f / fmaxf(sqrtf(sq), 1e-12f);
}

// layer1: feat1[r] = gather(src_seg) -> fp16; inv1[r] = 1/max(||feat1[r]||,eps)
__global__ void __launch_bounds__(256)
k_layer1() {
    int warp = (blockIdx.x * blockDim.x + threadIdx.x) >> 5;
    if (warp >= NPROP / 4) return;
    int lane = threadIdx.x & 31;
    int hl = lane & 7;
    int r = 4 * warp + (lane >> 3);

    int beg = g_ptr[r], deg = g_ptr[r + 1] - beg;
    int dmax = row_dmax(deg);

    const uint4* src;
    if (r < B1)      src = g_hi;
    else if (r < B2) src = g_hu;
    else if (r < B3) src = g_hb;
    else             src = g_hu;

    float2 acc[4];
    gather_row_hh2(src, beg, deg, dmax, hl, acc);

    uint4 p;
    p.x = f2h(acc[0].x, acc[0].y); p.y = f2h(acc[1].x, acc[1].y);
    p.z = f2h(acc[2].x, acc[2].y); p.w = f2h(acc[3].x, acc[3].y);
    g_f1h[r * 8 + hl] = p;

    float inv = row_inv_norm(acc);
    if (hl == 0) g_inv1[r] = inv;
}

// layer2: final = (base + feat1*inv1) + norm(gather(feat1_other_seg))
__global__ void __launch_bounds__(256)
k_layer2(float* __restrict__ out) {
    int warp = (blockIdx.x * blockDim.x + threadIdx.x) >> 5;
    if (warp >= NPROP / 4) return;
    int lane = threadIdx.x & 31;
    int hl = lane & 7;
    int r = 4 * warp + (lane >> 3);

    int beg = g_ptr[r], deg = g_ptr[r + 1] - beg;
    int dmax = row_dmax(deg);

    const uint4* src;
    const uint4* base;
    if (r < B1)      { src = g_f1h + B1 * 8; base = g_hu + r * 8; }
    else if (r < B2) { src = g_f1h;          base = g_hi + (r - B1) * 8; }
    else if (r < B3) { src = g_f1h + B3 * 8; base = g_hu + (r - B2) * 8; }
    else             { src = g_f1h + B2 * 8; base = g_hb + (r - B3) * 8; }

    float2 acc[4];
    gather_row_hh2(src, beg, deg, dmax, hl, acc);
    float inv = row_inv_norm(acc);

    uint4 bh = __ldcs(&base[hl]);
    uint4 fh = g_f1h[r * 8 + hl];
    float inv1 = g_inv1[r];
    float2 v[4];
    {
        float2 b0 = h2f(bh.x), b1 = h2f(bh.y), b2 = h2f(bh.z), b3 = h2f(bh.w);
        float2 f0 = h2f(fh.x), f1 = h2f(fh.y), f2 = h2f(fh.z), f3 = h2f(fh.w);
        v[0] = make_float2(b0.x + f0.x * inv1 + acc[0].x * inv, b0.y + f0.y * inv1 + acc[0].y * inv);
        v[1] = make_float2(b1.x + f1.x * inv1 + acc[1].x * inv, b1.y + f1.y * inv1 + acc[1].y * inv);
        v[2] = make_float2(b2.x + f2.x * inv1 + acc[2].x * inv, b2.y + f2.y * inv1 + acc[2].y * inv);
        v[3] = make_float2(b3.x + f3.x * inv1 + acc[3].x * inv, b3.y + f3.y * inv1 + acc[3].y * inv);
    }

    if (r >= B1 && r < B2) {
        uint4 p;
        p.x = f2h(v[0].x, v[0].y); p.y = f2h(v[1].x, v[1].y);
        p.z = f2h(v[2].x, v[2].y); p.w = f2h(v[3].x, v[3].y);
        g_aIh[(r - B1) * 8 + hl] = p;
    } else {
        float4 o0 = make_float4(v[0].x, v[0].y, v[1].x, v[1].y);
        float4 o1 = make_float4(v[2].x, v[2].y, v[3].x, v[3].y);
        float4* out4 = (float4*)out;
        int slot;
        if (r < B1)      slot = r * 32 + hl * 2;
        else if (r < B3) slot = (r - B2) * 32 + 16 + hl * 2;
        else             slot = (NU + r - B3) * 32 + 16 + hl * 2;
        __stcs(&out4[slot], o0);
        __stcs(&out4[slot + 1], o1);
    }
}

// rowmean: out[bundle, 0:64) = (1/(deg+1e-8)) * sum accI[i]   (fp32 accumulate)
__global__ void __launch_bounds__(256)
k_rowmean(float* __restrict__ out) {
    int warp = (blockIdx.x * blockDim.x + threadIdx.x) >> 5;
    if (warp >= NB / 4) return;
    int lane = threadIdx.x & 31;
    int hl = lane & 7;
    int b = 4 * warp + (lane >> 3);
    int r = B4 + b;

    int beg = g_ptr[r], deg = g_ptr[r + 1] - beg;
    int dmax = row_dmax(deg);

    float2 acc[4] = { {0.f,0.f},{0.f,0.f},{0.f,0.f},{0.f,0.f} };
    gather_row_h(g_aIh, beg, deg, dmax, hl, acc);

    float inv = 1.0f / ((float)deg + 1e-8f);
    float4 o0 = make_float4(acc[0].x * inv, acc[0].y * inv, acc[1].x * inv, acc[1].y * inv);
    float4 o1 = make_float4(acc[2].x * inv, acc[2].y * inv, acc[3].x * inv, acc[3].y * inv);
    float4* out4 = (float4*)out;
    int slot = (NU + b) * 32 + hl * 2;
    __stcs(&out4[slot], o0);
    __stcs(&out4[slot + 1], o1);
}

// ---------------------------------------------------------------------------
// Host launch sequence (graph-capturable, 6 launches)
// ---------------------------------------------------------------------------
extern "C" void kernel_launch(void* const* d_in, const int* in_sizes, int n_in,
                              void* d_out, int out_size) {
    const float4* users   = (const float4*)d_in[0];
    const float4* items   = (const float4*)d_in[1];
    const float4* bundles = (const float4*)d_in[2];
    const int4* ui_row = (const int4*)d_in[3];
    const int4* ui_col = (const int4*)d_in[4];
    const int4* ub_row = (const int4*)d_in[5];
    const int4* ub_col = (const int4*)d_in[6];
    const int4* bi_row = (const int4*)d_in[7];
    const int4* bi_col = (const int4*)d_in[8];
    float* out = (float*)d_out;

    const int T = 256;

    k_count_cvt<<<2048, T>>>(ui_row, ui_col, ub_row, ub_col, bi_row,
                             users, items, bundles);
    k_scan_lb<<<SCAN_NB, SCAN_T>>>();
    k_scatter<<<1024, T>>>(ui_row, ui_col, ub_row, ub_col, bi_row, bi_col);

    // 4 rows per warp: 8 warps = 32 rows per 256-thread block
    const int GP = (NPROP / 4 + 7) / 8;
    k_layer1<<<GP, T>>>();
    k_layer2<<<GP, T>>>(out);
    k_rowmean<<<(NB / 4 + 7) / 8, T>>>(out);
}